// round 2
// baseline (speedup 1.0000x reference)
#include <cuda_runtime.h>

#define NQ 12
#define NS 4096      // 2^NQ amplitudes
#define TPB 256
#define NL 3

// Precomputed fused per-(layer,wire) gates: RY(p2)@RZ(p1)@RY(p0), 8 floats each
__device__ float g_gates[NL * NQ * 8];

__global__ void prep_gates(const float* __restrict__ params) {
    int t = blockIdx.x * blockDim.x + threadIdx.x;
    if (t >= NL * NQ) return;
    float t0 = params[t * 3 + 0], t1 = params[t * 3 + 1], t2 = params[t * 3 + 2];
    float c0 = cosf(0.5f * t0), s0 = sinf(0.5f * t0);
    float cp = cosf(0.5f * t1), sp = sinf(0.5f * t1);
    float c2 = cosf(0.5f * t2), s2 = sinf(0.5f * t2);
    // p = exp(-i t1/2) = cp - i sp ; pbar = cp + i sp
    // RZ@RY0 = [[p c0, -p s0],[pbar s0, pbar c0]] = [[A,B],[C,D]]
    float A_re = cp * c0, A_im = -sp * c0;
    float B_re = -cp * s0, B_im = sp * s0;
    float C_re = cp * s0, C_im = sp * s0;
    float D_re = cp * c0, D_im = sp * c0;
    float* g = &g_gates[t * 8];
    g[0] = c2 * A_re - s2 * C_re;  g[1] = c2 * A_im - s2 * C_im;  // g00
    g[2] = c2 * B_re - s2 * D_re;  g[3] = c2 * B_im - s2 * D_im;  // g01
    g[4] = s2 * A_re + c2 * C_re;  g[5] = s2 * A_im + c2 * C_im;  // g10
    g[6] = s2 * B_re + c2 * D_re;  g[7] = s2 * B_im + c2 * D_im;  // g11
}

struct G2 { float2 g00, g01, g10, g11; };

__device__ __forceinline__ void apply_pair(const G2& g, float2& a, float2& b) {
    float2 na, nb;
    na.x = g.g00.x * a.x - g.g00.y * a.y + g.g01.x * b.x - g.g01.y * b.y;
    na.y = g.g00.x * a.y + g.g00.y * a.x + g.g01.x * b.y + g.g01.y * b.x;
    nb.x = g.g10.x * a.x - g.g10.y * a.y + g.g11.x * b.x - g.g11.y * b.y;
    nb.y = g.g10.x * a.y + g.g10.y * a.x + g.g11.x * b.y + g.g11.y * b.x;
    a = na; b = nb;
}

__device__ __forceinline__ G2 load_gate(const float* gsm, int l, int w) {
    const float* g = &gsm[(l * NQ + w) * 8];
    G2 r;
    r.g00 = make_float2(g[0], g[1]);
    r.g01 = make_float2(g[2], g[3]);
    r.g10 = make_float2(g[4], g[5]);
    r.g11 = make_float2(g[6], g[7]);
    return r;
}

__global__ __launch_bounds__(TPB) void qsim(
    const float* __restrict__ x, const float* __restrict__ head_w,
    const float* __restrict__ head_b, float* __restrict__ out) {
    __shared__ float2 st[NS];               // 32 KB statevector
    __shared__ float gsm[NL * NQ * 8];
    __shared__ float cs[2 * NQ];            // cos, sin of x/2 per wire
    __shared__ float wred[TPB / 32];

    int b = blockIdx.x, tid = threadIdx.x;

    // NL*NQ*8 = 288 > TPB, so this MUST be a strided loop (R1 bugfix)
    for (int i = tid; i < NL * NQ * 8; i += TPB) gsm[i] = g_gates[i];
    if (tid < NQ) {
        float xv = x[b * NQ + tid];
        cs[tid]      = cosf(0.5f * xv);
        cs[NQ + tid] = sinf(0.5f * xv);
    }
    __syncthreads();

    // --- RX encoding on |0..0> is a product state: build it directly ---
    // amp(idx) = prod_i (bit_i ? -i*sin : cos) = r * (-i)^popcount
    for (int i = tid; i < NS; i += TPB) {
        float r = 1.f; int k = 0;
        #pragma unroll
        for (int w = 0; w < NQ; w++) {
            int bit = (i >> (NQ - 1 - w)) & 1;
            r *= bit ? cs[NQ + w] : cs[w];
            k += bit;
        }
        int m = k & 3;
        float2 a;
        a.x = (m == 0) ? r : ((m == 2) ? -r : 0.f);
        a.y = (m == 1) ? -r : ((m == 3) ? r : 0.f);
        st[i] = a;
    }
    __syncthreads();

    // --- Layers: pass (w,w+1) applies G_{w+1} (+ G_0 on first pass) then CNOT(w,w+1) swap ---
    // Valid reordering: G_{w+1} commutes with all earlier CNOTs in the layer
    // (they act on wires <= w, disjoint from wire w+1).
    for (int l = 0; l < NL; l++) {
        for (int w = 0; w <= NQ - 2; w++) {
            G2 g1 = load_gate(gsm, l, w + 1);
            bool first = (w == 0);
            G2 g0;
            if (first) g0 = load_gate(gsm, l, 0);
            int lp = NQ - 2 - w;          // log2(post)
            int post = 1 << lp;
            for (int gi = tid; gi < NS / 4; gi += TPB) {
                int q = gi & (post - 1);
                int base = ((gi >> lp) << (lp + 2)) | q;
                float2 a0 = st[base];
                float2 a1 = st[base + post];
                float2 a2 = st[base + 2 * post];
                float2 a3 = st[base + 3 * post];
                apply_pair(g1, a0, a1);       // gate on wire w+1 (low bit of group)
                apply_pair(g1, a2, a3);
                if (first) {                   // gate on wire w (high bit), only first pass
                    apply_pair(g0, a0, a2);
                    apply_pair(g0, a1, a3);
                }
                // CNOT(w, w+1): control=high bit, target=low bit -> swap j=2,3
                st[base]            = a0;
                st[base + post]     = a1;
                st[base + 2 * post] = a3;
                st[base + 3 * post] = a2;
            }
            __syncthreads();
        }
    }

    // --- Readout: out[b] = sum_idx |a|^2 * (sum_i w_i * (1 - 2 bit_i)) + bias ---
    float hwr[NQ];
    #pragma unroll
    for (int w = 0; w < NQ; w++) hwr[w] = head_w[w];
    float acc = 0.f;
    for (int i = tid; i < NS; i += TPB) {
        float2 a = st[i];
        float p = a.x * a.x + a.y * a.y;
        float sw = 0.f;
        #pragma unroll
        for (int w = 0; w < NQ; w++)
            sw += ((i >> (NQ - 1 - w)) & 1) ? -hwr[w] : hwr[w];
        acc += p * sw;
    }
    #pragma unroll
    for (int o = 16; o > 0; o >>= 1) acc += __shfl_xor_sync(0xFFFFFFFFu, acc, o);
    if ((tid & 31) == 0) wred[tid >> 5] = acc;
    __syncthreads();
    if (tid == 0) {
        float tot = 0.f;
        #pragma unroll
        for (int i = 0; i < TPB / 32; i++) tot += wred[i];
        out[b] = tot + head_b[0];
    }
}

extern "C" void kernel_launch(void* const* d_in, const int* in_sizes, int n_in,
                              void* d_out, int out_size) {
    const float* x      = (const float*)d_in[0];
    const float* params = (const float*)d_in[1];
    const float* head_w = (const float*)d_in[2];
    const float* head_b = (const float*)d_in[3];
    float* out = (float*)d_out;
    int B = in_sizes[0] / NQ;
    prep_gates<<<1, 64>>>(params);
    qsim<<<B, TPB>>>(x, head_w, head_b, out);
}

// round 3
// speedup vs baseline: 2.1755x; 2.1755x over previous
#include <cuda_runtime.h>

#define NQ 12
#define NS 4096
#define TPB 256
#define NL 3

__device__ float g_gates[NL * NQ * 8];

__global__ void prep_gates(const float* __restrict__ params) {
    int t = blockIdx.x * blockDim.x + threadIdx.x;
    if (t >= NL * NQ) return;
    float t0 = params[t * 3 + 0], t1 = params[t * 3 + 1], t2 = params[t * 3 + 2];
    float c0 = cosf(0.5f * t0), s0 = sinf(0.5f * t0);
    float cp = cosf(0.5f * t1), sp = sinf(0.5f * t1);
    float c2 = cosf(0.5f * t2), s2 = sinf(0.5f * t2);
    float A_re = cp * c0, A_im = -sp * c0;
    float B_re = -cp * s0, B_im = sp * s0;
    float C_re = cp * s0, C_im = sp * s0;
    float D_re = cp * c0, D_im = sp * c0;
    float* g = &g_gates[t * 8];
    g[0] = c2 * A_re - s2 * C_re;  g[1] = c2 * A_im - s2 * C_im;
    g[2] = c2 * B_re - s2 * D_re;  g[3] = c2 * B_im - s2 * D_im;
    g[4] = s2 * A_re + c2 * C_re;  g[5] = s2 * A_im + c2 * C_im;
    g[6] = s2 * B_re + c2 * D_re;  g[7] = s2 * B_im + c2 * D_im;
}

struct G2 { float2 g00, g01, g10, g11; };

__device__ __forceinline__ void apply_pair(const G2& g, float2& a, float2& b) {
    float2 na, nb;
    na.x = g.g00.x * a.x - g.g00.y * a.y + g.g01.x * b.x - g.g01.y * b.y;
    na.y = g.g00.x * a.y + g.g00.y * a.x + g.g01.x * b.y + g.g01.y * b.x;
    nb.x = g.g10.x * a.x - g.g10.y * a.y + g.g11.x * b.x - g.g11.y * b.y;
    nb.y = g.g10.x * a.y + g.g10.y * a.x + g.g11.x * b.y + g.g11.y * b.x;
    a = na; b = nb;
}

__device__ __forceinline__ G2 load_gate(const float* gsm, int l, int w) {
    const float* g = &gsm[(l * NQ + w) * 8];
    G2 r;
    r.g00 = make_float2(g[0], g[1]);
    r.g01 = make_float2(g[2], g[3]);
    r.g10 = make_float2(g[4], g[5]);
    r.g11 = make_float2(g[6], g[7]);
    return r;
}

// gate on local bit K of the 16-amp register file
__device__ __forceinline__ void gate_on_bit(const G2& g, float2 r[16], int k) {
    #pragma unroll
    for (int l = 0; l < 16; l++)
        if (!(l & (1 << k))) apply_pair(g, r[l], r[l | (1 << k)]);
}

// CNOT: control local bit c, target local bit tg (pure register swap)
__device__ __forceinline__ void cnot_loc(float2 r[16], int c, int tg) {
    #pragma unroll
    for (int l = 0; l < 16; l++)
        if ((l & (1 << c)) && !(l & (1 << tg))) {
            float2 tmp = r[l]; r[l] = r[l | (1 << tg)]; r[l | (1 << tg)] = tmp;
        }
}

// Stage index->global-index maps. t = thread (8 bits), l = local (4 bits).
// S0 local bits g[11:8] (wires 0-3), S1 g[8:5] (wires 3-6),
// S2 g[5:2] (wires 6-9),  S3 g[3:0] (wires 8-11).
__device__ __forceinline__ int gS0(int t, int l) { return (l << 8) | t; }
__device__ __forceinline__ int gS1(int t, int l) { return ((t >> 5) << 9) | (l << 5) | (t & 31); }
__device__ __forceinline__ int gS2(int t, int l) { return ((t >> 5) << 9) | (((t >> 2) & 7) << 6) | (l << 2) | (t & 3); }
__device__ __forceinline__ int gS3(int t, int l) { return ((t >> 5) << 9) | ((t & 31) << 4) | l; }
__device__ __forceinline__ int swz(int g, int m) { return g ^ ((g >> 4) & m); }

__global__ __launch_bounds__(TPB) void qsim(
    const float* __restrict__ x, const float* __restrict__ head_w,
    const float* __restrict__ head_b, float* __restrict__ out) {
    __shared__ float2 st[NS];          // 32 KB transpose buffer
    __shared__ float gsm[NL * NQ * 8];
    __shared__ float csC[NQ], csS[NQ];
    __shared__ float wred[TPB / 32];

    int b = blockIdx.x, t = threadIdx.x;

    for (int i = t; i < NL * NQ * 8; i += TPB) gsm[i] = g_gates[i];
    if (t < NQ) {
        float xv = x[b * NQ + t];
        csC[t] = cosf(0.5f * xv);
        csS[t] = sinf(0.5f * xv);
    }
    __syncthreads();

    float2 r[16];

    // --- Init: product state amp(g) = prod_w (bit? -i*sin : cos), built in S0 layout.
    // Thread bits t = g[7:0] = wires 4..11; local l = g[11:8] = wires 0..3.
    {
        float rB = 1.f;
        #pragma unroll
        for (int w = 4; w < NQ; w++) {
            int bit = (t >> (11 - w)) & 1;
            rB *= bit ? csS[w] : csC[w];
        }
        int kB = __popc(t & 0xFF);
        #pragma unroll
        for (int l = 0; l < 16; l++) {
            float rA = 1.f;
            #pragma unroll
            for (int w = 0; w < 4; w++) {
                int bit = (l >> (3 - w)) & 1;
                rA *= bit ? csS[w] : csC[w];
            }
            float v = rA * rB;
            int m = (kB + __popc(l)) & 3;   // (-i)^m
            float2 a;
            a.x = (m == 0) ? v : ((m == 2) ? -v : 0.f);
            a.y = (m == 1) ? -v : ((m == 3) ? v : 0.f);
            r[l] = a;
        }
    }

    #define XPOSE(GSRC, GDST, MASK) do {                              \
        __syncthreads();                                              \
        _Pragma("unroll")                                             \
        for (int i_ = 0; i_ < 16; i_++) st[swz(GSRC(t, i_), MASK)] = r[i_]; \
        __syncthreads();                                              \
        _Pragma("unroll")                                             \
        for (int i_ = 0; i_ < 16; i_++) r[i_] = st[swz(GDST(t, i_), MASK)]; \
    } while (0)

    for (int l = 0; l < NL; l++) {
        // S0: wires 0-3 on local bits 3..0
        {
            G2 G0 = load_gate(gsm, l, 0), G1 = load_gate(gsm, l, 1);
            G2 G2_ = load_gate(gsm, l, 2), G3 = load_gate(gsm, l, 3);
            gate_on_bit(G0, r, 3); gate_on_bit(G1, r, 2);
            gate_on_bit(G2_, r, 1); gate_on_bit(G3, r, 0);
            cnot_loc(r, 3, 2); cnot_loc(r, 2, 1); cnot_loc(r, 1, 0);
        }
        XPOSE(gS0, gS1, 0);
        // S1: wires 3(l3),4(l2),5(l1),6(l0); gates on 4,5,6
        {
            G2 G4 = load_gate(gsm, l, 4), G5 = load_gate(gsm, l, 5), G6 = load_gate(gsm, l, 6);
            gate_on_bit(G4, r, 2); gate_on_bit(G5, r, 1); gate_on_bit(G6, r, 0);
            cnot_loc(r, 3, 2); cnot_loc(r, 2, 1); cnot_loc(r, 1, 0);
        }
        XPOSE(gS1, gS2, 0xC);
        // S2: wires 6(l3),7(l2),8(l1),9(l0); gates on 7,8,9
        {
            G2 G7 = load_gate(gsm, l, 7), G8 = load_gate(gsm, l, 8), G9 = load_gate(gsm, l, 9);
            gate_on_bit(G7, r, 2); gate_on_bit(G8, r, 1); gate_on_bit(G9, r, 0);
            cnot_loc(r, 3, 2); cnot_loc(r, 2, 1); cnot_loc(r, 1, 0);
        }
        XPOSE(gS2, gS3, 0xF);
        // S3: wires 8(l3),9(l2),10(l1),11(l0); gates on 10,11
        {
            G2 Ga = load_gate(gsm, l, 10), Gb = load_gate(gsm, l, 11);
            gate_on_bit(Ga, r, 1); gate_on_bit(Gb, r, 0);
            cnot_loc(r, 2, 1); cnot_loc(r, 1, 0);
        }
        if (l < NL - 1) XPOSE(gS3, gS0, 0xF);
    }

    // --- Readout directly from S3 registers ---
    float hw[NQ];
    #pragma unroll
    for (int w = 0; w < NQ; w++) hw[w] = head_w[w];
    // thread part: wires 0..7 live in g bits 11..4
    float swt = 0.f;
    #pragma unroll
    for (int w = 0; w < 8; w++) {
        int g = gS3(t, 0);
        swt += ((g >> (11 - w)) & 1) ? -hw[w] : hw[w];
    }
    float acc = 0.f;
    #pragma unroll
    for (int l = 0; l < 16; l++) {
        float2 a = r[l];
        float p = a.x * a.x + a.y * a.y;
        float swl = 0.f;
        #pragma unroll
        for (int w = 8; w < 12; w++)
            swl += ((l >> (11 - w)) & 1) ? -hw[w] : hw[w];
        acc += p * (swt + swl);
    }
    #pragma unroll
    for (int o = 16; o > 0; o >>= 1) acc += __shfl_xor_sync(0xFFFFFFFFu, acc, o);
    if ((t & 31) == 0) wred[t >> 5] = acc;
    __syncthreads();
    if (t == 0) {
        float tot = 0.f;
        #pragma unroll
        for (int i = 0; i < TPB / 32; i++) tot += wred[i];
        out[b] = tot + head_b[0];
    }
}

extern "C" void kernel_launch(void* const* d_in, const int* in_sizes, int n_in,
                              void* d_out, int out_size) {
    const float* x      = (const float*)d_in[0];
    const float* params = (const float*)d_in[1];
    const float* head_w = (const float*)d_in[2];
    const float* head_b = (const float*)d_in[3];
    float* out = (float*)d_out;
    int B = in_sizes[0] / NQ;
    prep_gates<<<1, 64>>>(params);
    qsim<<<B, TPB>>>(x, head_w, head_b, out);
}